// round 15
// baseline (speedup 1.0000x reference)
#include <cuda_runtime.h>
#include <cuda_bf16.h>

#define IMG_S 4096
#define NDOTS 100
#define TILE_W 64
#define TILE_H 16
#define NTHREADS 256

__global__ __launch_bounds__(NTHREADS)
void patch_dots_kernel(const float* __restrict__ patch,
                       const float* __restrict__ centers,
                       const float* __restrict__ radii,
                       const float* __restrict__ colors,
                       float* __restrict__ out)
{
    // Compact per-tile work list, descending dot index (highest first).
    __shared__ float4 sgeo[NDOTS];   // {cx, cy, r2, -}
    __shared__ float4 scol[NDOTS];   // {r, g, b, -}
    __shared__ unsigned s_mi[4];     // intersect ballots
    __shared__ unsigned s_mf[4];     // full-cover ballots
    __shared__ int s_cnt;
    __shared__ int s_jmax;

    const int tid  = threadIdx.x;
    const int lane = tid & 31;
    const int wrp  = tid >> 5;

    const int tx0 = (blockIdx.x & 63) * TILE_W;
    const int ty0 = (blockIdx.x >> 6) * TILE_H;

    // ========== Cull phase 1: one ballot round (warps 0..3, dots 0..127) ==========
    float cx = 0.f, cy = 0.f, r2 = -1.f, ccr = 0.f, ccg = 0.f, ccb = 0.f;

    if (tid < 128) {
        bool isect = false, full = false;
        if (tid < NDOTS) {
            cx = floorf(centers[2 * tid + 0] * (float)IMG_S);
            cy = floorf(centers[2 * tid + 1] * (float)IMG_S);
            float r = floorf(radii[tid] * ((float)IMG_S / 5.0f));
            r2 = r * r;
            ccr = colors[3 * tid + 0];
            ccg = colors[3 * tid + 1];
            ccb = colors[3 * tid + 2];

            float x0 = (float)tx0, x1 = (float)(tx0 + TILE_W - 1);
            float y0 = (float)ty0, y1 = (float)(ty0 + TILE_H - 1);
            float nx = fminf(fmaxf(cx, x0), x1) - cx;
            float ny = fminf(fmaxf(cy, y0), y1) - cy;
            isect = fmaf(nx, nx, ny * ny) <= r2;
            float fxd = fmaxf(fabsf(x0 - cx), fabsf(x1 - cx));
            float fyd = fmaxf(fabsf(y0 - cy), fabsf(y1 - cy));
            full = fmaf(fxd, fxd, fyd * fyd) <= r2;
        }
        unsigned mi = __ballot_sync(0xFFFFFFFFu, isect);
        unsigned mf = __ballot_sync(0xFFFFFFFFu, full);
        if (lane == 0) { s_mi[wrp] = mi; s_mf[wrp] = mf; }
    }
    __syncthreads();

    // ========== Cull phase 2: derive jmax + compaction slot locally ==========
    if (tid < 128) {
        const unsigned f0 = s_mf[0], f1 = s_mf[1], f2 = s_mf[2], f3 = s_mf[3];
        int jmax = -1;
        if (f3)      jmax = 96 + (31 - __clz(f3));
        else if (f2) jmax = 64 + (31 - __clz(f2));
        else if (f1) jmax = 32 + (31 - __clz(f1));
        else if (f0) jmax =      (31 - __clz(f0));

        unsigned a0 = s_mi[0], a1 = s_mi[1], a2 = s_mi[2], a3 = s_mi[3];
        if (jmax >= 96)      { a0 = a1 = a2 = 0; a3 &= 0xFFFFFFFFu << (jmax - 96); }
        else if (jmax >= 64) { a0 = a1 = 0;      a2 &= 0xFFFFFFFFu << (jmax - 64); }
        else if (jmax >= 32) { a0 = 0;           a1 &= 0xFFFFFFFFu << (jmax - 32); }
        else if (jmax >= 0)  {                   a0 &= 0xFFFFFFFFu <<  jmax;       }

        const unsigned myw = (wrp == 0) ? a0 : (wrp == 1) ? a1 : (wrp == 2) ? a2 : a3;
        const bool alive = (myw >> lane) & 1u;
        if (alive) {
            // slot = number of surviving dots with index > tid  (descending order)
            int slot = __popc(myw & (0xFFFFFFFEu << lane));
            if (wrp < 3) slot += __popc(a3);
            if (wrp < 2) slot += __popc(a2);
            if (wrp < 1) slot += __popc(a1);
            sgeo[slot] = make_float4(cx, cy, r2, 0.f);
            scol[slot] = make_float4(ccr, ccg, ccb, 0.f);
        }
        if (tid == 0) {
            s_cnt  = __popc(a0) + __popc(a1) + __popc(a2) + __popc(a3);
            s_jmax = jmax;
        }
    }
    __syncthreads();

    // ================= Pixel phase: one quad (4 px) per thread =================
    const int lx = (tid & 15) * 4;       // 0..60
    const int ly = tid >> 4;             // 0..15
    const int x  = tx0 + lx;
    const int y  = ty0 + ly;

    const unsigned plane_q = (IMG_S / 4) * IMG_S;
    const unsigned qidx = (unsigned)y * (IMG_S / 4) + (unsigned)(x >> 2);
    const float4* __restrict__ p4 = (const float4*)patch;
    float4* __restrict__ o4 = (float4*)out;

    const int cnt = s_cnt;

    float4 vr, vg, vb;

    if (s_jmax >= 0 && cnt == 1) {
        // Uniform tile: single color everywhere.
        const float4 c = scol[0];
        vr = make_float4(c.x, c.x, c.x, c.x);
        vg = make_float4(c.y, c.y, c.y, c.y);
        vb = make_float4(c.z, c.z, c.z, c.z);
    } else {
        const float fx = (float)x;
        const float fy = (float)y;
        int i0 = -1, i1 = -1, i2 = -1, i3 = -1;

        // Software-pipelined scan: prefetch next dot while testing current,
        // hiding the 29-cycle LDS latency behind the FFMA/SETP chain.
        float4 g = sgeo[0];
        #pragma unroll 1
        for (int j = 0; j < cnt; ++j) {
            const int jn = (j + 1 < cnt) ? j + 1 : j;
            const float4 gn = sgeo[jn];          // prefetch next (independent)
            const float dy  = fy - g.y;
            const float dy2 = dy * dy;
            const float dx0 = fx - g.x;
            const float dx1 = dx0 + 1.0f;
            const float dx2 = dx0 + 2.0f;
            const float dx3 = dx0 + 3.0f;
            if (i0 < 0 && fmaf(dx0, dx0, dy2) <= g.z) i0 = j;
            if (i1 < 0 && fmaf(dx1, dx1, dy2) <= g.z) i1 = j;
            if (i2 < 0 && fmaf(dx2, dx2, dy2) <= g.z) i2 = j;
            if (i3 < 0 && fmaf(dx3, dx3, dy2) <= g.z) i3 = j;
            if ((i0 | i1 | i2 | i3) >= 0) break;   // all lanes resolved
            g = gn;
        }

        // Colors for resolved lanes (clamped indices are safe).
        const float4 c0 = scol[i0 < 0 ? 0 : i0];
        const float4 c1 = scol[i1 < 0 ? 0 : i1];
        const float4 c2 = scol[i2 < 0 ? 0 : i2];
        const float4 c3 = scol[i3 < 0 ? 0 : i3];
        vr = make_float4(c0.x, c1.x, c2.x, c3.x);
        vg = make_float4(c0.y, c1.y, c2.y, c3.y);
        vb = make_float4(c0.z, c1.z, c2.z, c3.z);

        // Demand-load patch ONLY if some lane is uncovered (~2% of quads).
        if ((i0 | i1 | i2 | i3) < 0) {
            const float4 pr = p4[qidx];
            const float4 pg = p4[qidx + plane_q];
            const float4 pb = p4[qidx + 2 * plane_q];
            if (i0 < 0) { vr.x = pr.x; vg.x = pg.x; vb.x = pb.x; }
            if (i1 < 0) { vr.y = pr.y; vg.y = pg.y; vb.y = pb.y; }
            if (i2 < 0) { vr.z = pr.z; vg.z = pg.z; vb.z = pb.z; }
            if (i3 < 0) { vr.w = pr.w; vg.w = pg.w; vb.w = pb.w; }
        }
    }

    // Streaming stores: output is write-once, never re-read by this kernel.
    __stcs(&o4[qidx],               vr);
    __stcs(&o4[qidx + plane_q],     vg);
    __stcs(&o4[qidx + 2 * plane_q], vb);
}

extern "C" void kernel_launch(void* const* d_in, const int* in_sizes, int n_in,
                              void* d_out, int out_size)
{
    const float* patch   = (const float*)d_in[0];
    const float* centers = (const float*)d_in[1];
    const float* radii   = (const float*)d_in[2];
    const float* colors  = (const float*)d_in[3];
    float* out = (float*)d_out;

    const int blocks = (IMG_S / TILE_W) * (IMG_S / TILE_H);   // 16384
    patch_dots_kernel<<<blocks, NTHREADS>>>(patch, centers, radii, colors, out);
}